// round 17
// baseline (speedup 1.0000x reference)
#include <cuda_runtime.h>
#include <cuda_fp16.h>
#include <cstdint>

#define N_MAX 100000
#define E_MAX 1000000
#define D 64
#define TILE_ROWS 128
#define SCAN_B 1024
#define XS_STRIDE 36        // u32 per xs row (144B) -> bank = 4g+tg, conflict-free
#define WT_STRIDE 36        // u32 per wt row

// Scratch (static device globals — no allocations allowed)
__device__ int    g_deg     [N_MAX];
__device__ int    g_rowptr  [N_MAX + 1];
__device__ int    g_rank    [E_MAX];        // per-edge rank within dst bucket
__device__ int    g_srcsort [E_MAX];
__device__ volatile int g_scan_total[128];  // block totals (published)
__device__ volatile int g_scan_flag [128];  // publication flags
__device__ float  s_dinv    [N_MAX];
__device__ uint4  s_h       [N_MAX * 8];    // fp16 gather source: 64 halves/row
__device__ uint4  s_yh      [N_MAX * 8];    // layer-1 output, fp16

// ---------------------------------------------------------------------------
// edge_index is INT32 on device (JAX x64 disabled canonicalizes int64->int32).
// Histogram with returned rank -> placement below needs no atomics.
__global__ void hist_rank_kernel(const int* __restrict__ ei, int E) {
    int e = blockIdx.x * blockDim.x + threadIdx.x;
    if (e < E) g_rank[e] = atomicAdd(&g_deg[ei[E + e]], 1);
}

// ---------------------------------------------------------------------------
// Single-kernel exclusive scan + dinv (decoupled-lookback-lite).
// Grid is <= 98 blocks of 1024 (one wave on 148 SMs -> all co-resident, so
// spin-waiting on other blocks' published totals cannot deadlock).
__global__ __launch_bounds__(SCAN_B) void scan_fused_kernel(int n, int E, int nb) {
    __shared__ int wsums[32];
    __shared__ int red[128];
    __shared__ int offset;

    int t = threadIdx.x, lane = t & 31, w = t >> 5;
    int i = blockIdx.x * SCAN_B + t;
    int orig = (i < n) ? g_deg[i] : 0;

    // block-local inclusive scan (shuffle)
    int v = orig;
    #pragma unroll
    for (int o = 1; o < 32; o <<= 1) {
        int u = __shfl_up_sync(0xffffffffu, v, o);
        if (lane >= o) v += u;
    }
    if (lane == 31) wsums[w] = v;
    __syncthreads();
    if (w == 0) {
        int s = wsums[lane];
        #pragma unroll
        for (int o = 1; o < 32; o <<= 1) {
            int u = __shfl_up_sync(0xffffffffu, s, o);
            if (lane >= o) s += u;
        }
        wsums[lane] = s;
    }
    __syncthreads();
    int incl = v + ((w > 0) ? wsums[w - 1] : 0);

    // publish this block's total
    if (t == SCAN_B - 1) {
        g_scan_total[blockIdx.x] = incl;
        __threadfence();
        g_scan_flag[blockIdx.x] = 1;
    }

    // gather predecessors' totals (spin; all blocks co-resident)
    int myv = 0;
    if (t < 128) {
        if (t < (int)blockIdx.x) {
            while (g_scan_flag[t] == 0) { }
            myv = g_scan_total[t];
        }
        red[t] = myv;
    }
    __syncthreads();
    if (t < 64) red[t] += red[t + 64];
    __syncthreads();
    if (t < 32) {
        int s = red[t] + red[t + 32];
        #pragma unroll
        for (int o = 16; o > 0; o >>= 1) s += __shfl_down_sync(0xffffffffu, s, o);
        if (t == 0) offset = s;
    }
    __syncthreads();

    if (i < n) {
        g_rowptr[i] = incl - orig + offset;           // exclusive + offset
        s_dinv[i] = rsqrtf((float)orig + 1.0f);       // +1 self loop
    }
    if (i == 0) g_rowptr[n] = E;
}

// atomic-free placement: pos = rowptr[dst] + rank[e]
__global__ void place_kernel(const int* __restrict__ ei, int E) {
    int e = blockIdx.x * blockDim.x + threadIdx.x;
    if (e < E) {
        int src = __ldg(&ei[e]);
        int dst = __ldg(&ei[E + e]);
        int pos = __ldg(&g_rowptr[dst]) + g_rank[e];
        g_srcsort[pos] = src;
    }
}

// ---------------------------------------------------------------------------
// Tensor-core GEMM: h = dinv * (X @ W), fp16 store to s_h.
// mma.sync m16n8k16 f32.f16.f16.f32. 256 threads = 8 warps; warp computes
// 16 rows x 64 cols. W transposed to [n][k] fp16 in smem.
template <bool IN_HALF>
__device__ __forceinline__ void gemm_mma_body(
    const void* __restrict__ Xv, const float* __restrict__ W,
    int n, int row0, uint32_t* xs, uint32_t* wt)
{
    const int tid = threadIdx.x;

    __half* wt_h = (__half*)wt;
    #pragma unroll
    for (int i = tid; i < D * D; i += 256) {
        int k = i >> 6, nn = i & 63;
        wt_h[nn * (WT_STRIDE * 2) + k] = __float2half(__ldg(&W[i]));
    }

    #pragma unroll
    for (int i = tid; i < TILE_ROWS * 32; i += 256) {
        int r = i >> 5, c = i & 31;
        uint32_t u = 0u;
        if (row0 + r < n) {
            if (IN_HALF) {
                u = __ldg(&((const uint32_t*)Xv)[(row0 + r) * 32 + c]);
            } else {
                float2 v = __ldg(&((const float2*)Xv)[(row0 + r) * 32 + c]);
                __half2 p = __floats2half2_rn(v.x, v.y);
                u = *(uint32_t*)&p;
            }
        }
        xs[r * XS_STRIDE + c] = u;
    }
    __syncthreads();

    const int warp = tid >> 5, lane = tid & 31;
    const int g = lane >> 2, tg = lane & 3;
    const int r_lo = warp * 16 + g;

    float c[8][4];
    #pragma unroll
    for (int nb = 0; nb < 8; nb++)
        #pragma unroll
        for (int q = 0; q < 4; q++) c[nb][q] = 0.f;

    const uint32_t* xlo = xs + r_lo * XS_STRIDE;
    const uint32_t* xhi = xs + (r_lo + 8) * XS_STRIDE;

    #pragma unroll
    for (int kc = 0; kc < 4; kc++) {
        uint32_t a0 = xlo[kc * 8 + tg];
        uint32_t a1 = xhi[kc * 8 + tg];
        uint32_t a2 = xlo[kc * 8 + 4 + tg];
        uint32_t a3 = xhi[kc * 8 + 4 + tg];
        #pragma unroll
        for (int nb = 0; nb < 8; nb++) {
            int nn = nb * 8 + g;
            uint32_t b0 = wt[nn * WT_STRIDE + kc * 8 + tg];
            uint32_t b1 = wt[nn * WT_STRIDE + kc * 8 + 4 + tg];
            asm volatile(
                "mma.sync.aligned.m16n8k16.row.col.f32.f16.f16.f32 "
                "{%0,%1,%2,%3}, {%4,%5,%6,%7}, {%8,%9}, {%0,%1,%2,%3};"
                : "+f"(c[nb][0]), "+f"(c[nb][1]), "+f"(c[nb][2]), "+f"(c[nb][3])
                : "r"(a0), "r"(a1), "r"(a2), "r"(a3), "r"(b0), "r"(b1));
        }
    }

    int grow_lo = row0 + r_lo, grow_hi = grow_lo + 8;
    float dlo = (grow_lo < n) ? s_dinv[grow_lo] : 0.f;
    float dhi = (grow_hi < n) ? s_dinv[grow_hi] : 0.f;
    uint32_t* H = (uint32_t*)s_h;
    #pragma unroll
    for (int nb = 0; nb < 8; nb++) {
        if (grow_lo < n) {
            __half2 p = __floats2half2_rn(c[nb][0] * dlo, c[nb][1] * dlo);
            H[grow_lo * 32 + nb * 4 + tg] = *(uint32_t*)&p;
        }
        if (grow_hi < n) {
            __half2 p = __floats2half2_rn(c[nb][2] * dhi, c[nb][3] * dhi);
            H[grow_hi * 32 + nb * 4 + tg] = *(uint32_t*)&p;
        }
    }
}

__global__ __launch_bounds__(256) void gemm1_kernel(
    const float* __restrict__ X, const float* __restrict__ W, int n)
{
    __shared__ uint32_t xs[TILE_ROWS * XS_STRIDE];
    __shared__ uint32_t wt[D * WT_STRIDE];
    gemm_mma_body<false>(X, W, n, blockIdx.x * TILE_ROWS, xs, wt);
}

__global__ __launch_bounds__(256) void gemm2_kernel(
    const float* __restrict__ W, int n)
{
    __shared__ uint32_t xs[TILE_ROWS * XS_STRIDE];
    __shared__ uint32_t wt[D * WT_STRIDE];
    gemm_mma_body<true>(s_yh, W, n, blockIdx.x * TILE_ROWS, xs, wt);
}

// ---------------------------------------------------------------------------
__device__ __forceinline__ void acc_add8(float acc[8], uint4 u) {
    float2 f0 = __half22float2(*(__half2*)&u.x);
    float2 f1 = __half22float2(*(__half2*)&u.y);
    float2 f2 = __half22float2(*(__half2*)&u.z);
    float2 f3 = __half22float2(*(__half2*)&u.w);
    acc[0] += f0.x; acc[1] += f0.y; acc[2] += f1.x; acc[3] += f1.y;
    acc[4] += f2.x; acc[5] += f2.y; acc[6] += f3.x; acc[7] += f3.y;
}

// Gather-aggregate + epilogue. 8 threads/node, one uint4 each. Batch-8 then
// batch-4 then scalar (deeper MLP vs ~250cyc L2 latency).
template <bool OUT_HALF>
__global__ __launch_bounds__(256) void aggregate_kernel(
    const float* __restrict__ b, void* __restrict__ out, int n)
{
    int idx = blockIdx.x * blockDim.x + threadIdx.x;
    int v = idx >> 3;
    if (v >= n) return;
    int j = idx & 7;

    float acc[8];
    #pragma unroll
    for (int c = 0; c < 8; c++) acc[c] = 0.f;
    acc_add8(acc, __ldg(&s_h[v * 8 + j]));             // self loop

    int beg = __ldg(&g_rowptr[v]);
    int end = __ldg(&g_rowptr[v + 1]);

    int k = beg;
    #pragma unroll 1
    for (; k + 8 <= end; k += 8) {
        int s0 = __ldg(&g_srcsort[k + 0]);
        int s1 = __ldg(&g_srcsort[k + 1]);
        int s2 = __ldg(&g_srcsort[k + 2]);
        int s3 = __ldg(&g_srcsort[k + 3]);
        int s4 = __ldg(&g_srcsort[k + 4]);
        int s5 = __ldg(&g_srcsort[k + 5]);
        int s6 = __ldg(&g_srcsort[k + 6]);
        int s7 = __ldg(&g_srcsort[k + 7]);
        uint4 u0 = __ldg(&s_h[s0 * 8 + j]);
        uint4 u1 = __ldg(&s_h[s1 * 8 + j]);
        uint4 u2 = __ldg(&s_h[s2 * 8 + j]);
        uint4 u3 = __ldg(&s_h[s3 * 8 + j]);
        uint4 u4 = __ldg(&s_h[s4 * 8 + j]);
        uint4 u5 = __ldg(&s_h[s5 * 8 + j]);
        uint4 u6 = __ldg(&s_h[s6 * 8 + j]);
        uint4 u7 = __ldg(&s_h[s7 * 8 + j]);
        acc_add8(acc, u0); acc_add8(acc, u1);
        acc_add8(acc, u2); acc_add8(acc, u3);
        acc_add8(acc, u4); acc_add8(acc, u5);
        acc_add8(acc, u6); acc_add8(acc, u7);
    }
    if (k + 4 <= end) {
        int s0 = __ldg(&g_srcsort[k + 0]);
        int s1 = __ldg(&g_srcsort[k + 1]);
        int s2 = __ldg(&g_srcsort[k + 2]);
        int s3 = __ldg(&g_srcsort[k + 3]);
        uint4 u0 = __ldg(&s_h[s0 * 8 + j]);
        uint4 u1 = __ldg(&s_h[s1 * 8 + j]);
        uint4 u2 = __ldg(&s_h[s2 * 8 + j]);
        uint4 u3 = __ldg(&s_h[s3 * 8 + j]);
        acc_add8(acc, u0); acc_add8(acc, u1);
        acc_add8(acc, u2); acc_add8(acc, u3);
        k += 4;
    }
    for (; k < end; k++) {
        int s = __ldg(&g_srcsort[k]);
        acc_add8(acc, __ldg(&s_h[s * 8 + j]));
    }

    float dv = __ldg(&s_dinv[v]);
    const float4* b4 = (const float4*)b;
    float4 bb0 = __ldg(&b4[j * 2 + 0]);
    float4 bb1 = __ldg(&b4[j * 2 + 1]);
    float o[8];
    o[0] = fmaxf(fmaf(acc[0], dv, bb0.x), 0.f);
    o[1] = fmaxf(fmaf(acc[1], dv, bb0.y), 0.f);
    o[2] = fmaxf(fmaf(acc[2], dv, bb0.z), 0.f);
    o[3] = fmaxf(fmaf(acc[3], dv, bb0.w), 0.f);
    o[4] = fmaxf(fmaf(acc[4], dv, bb1.x), 0.f);
    o[5] = fmaxf(fmaf(acc[5], dv, bb1.y), 0.f);
    o[6] = fmaxf(fmaf(acc[6], dv, bb1.z), 0.f);
    o[7] = fmaxf(fmaf(acc[7], dv, bb1.w), 0.f);

    if (OUT_HALF) {
        __half2 p0 = __floats2half2_rn(o[0], o[1]);
        __half2 p1 = __floats2half2_rn(o[2], o[3]);
        __half2 p2 = __floats2half2_rn(o[4], o[5]);
        __half2 p3 = __floats2half2_rn(o[6], o[7]);
        uint4 u;
        u.x = *(unsigned int*)&p0;
        u.y = *(unsigned int*)&p1;
        u.z = *(unsigned int*)&p2;
        u.w = *(unsigned int*)&p3;
        ((uint4*)out)[v * 8 + j] = u;
    } else {
        float4* O4 = (float4*)out;
        O4[v * 16 + j * 2 + 0] = make_float4(o[0], o[1], o[2], o[3]);
        O4[v * 16 + j * 2 + 1] = make_float4(o[4], o[5], o[6], o[7]);
    }
}

// ---------------------------------------------------------------------------
extern "C" void kernel_launch(void* const* d_in, const int* in_sizes, int n_in,
                              void* d_out, int out_size)
{
    const float* x  = (const float*)d_in[0];
    const int*   ei = (const int*)d_in[1];      // int32 (JAX x64 disabled)
    const float* W1 = (const float*)d_in[2];
    const float* b1 = (const float*)d_in[3];
    const float* W2 = (const float*)d_in[4];
    const float* b2 = (const float*)d_in[5];

    const int n = in_sizes[0] / D;        // 100000
    const int E = in_sizes[1] / 2;        // 1000000

    const int nb_e   = (E + 255) / 256;
    const int nb_sc  = (n + SCAN_B - 1) / SCAN_B;   // 98 <= 148 (one wave)
    const int nb_gmm = (n + TILE_ROWS - 1) / TILE_ROWS;
    const int nb_agg = (n * 8 + 255) / 256;

    // zero degree counters + scan flags/totals (graph memset nodes)
    void* degp = nullptr;
    cudaGetSymbolAddress(&degp, g_deg);
    cudaMemsetAsync(degp, 0, (size_t)n * sizeof(int));
    void* flagp = nullptr;
    cudaGetSymbolAddress(&flagp, (const void*)g_scan_flag);
    cudaMemsetAsync(flagp, 0, 128 * sizeof(int));

    void* yh = nullptr;
    cudaGetSymbolAddress(&yh, s_yh);

    // --- graph preprocessing ---
    hist_rank_kernel<<<nb_e, 256>>>(ei, E);
    scan_fused_kernel<<<nb_sc, SCAN_B>>>(n, E, nb_sc);
    place_kernel<<<nb_e, 256>>>(ei, E);

    // layer 1 (tensor-core GEMM)
    gemm1_kernel<<<nb_gmm, 256>>>(x, W1, n);
    aggregate_kernel<true><<<nb_agg, 256>>>(b1, yh, n);

    // layer 2
    gemm2_kernel<<<nb_gmm, 256>>>(W2, n);
    aggregate_kernel<false><<<nb_agg, 256>>>(b2, d_out, n);
}